// round 1
// baseline (speedup 1.0000x reference)
#include <cuda_runtime.h>
#include <cuda_bf16.h>

// GCN: 5 layers, N<=100000 nodes, E edges, IN_F=128, HID=64.
// agg[c] = dinv[c] * ( sum_{e: col=c} s[row[e]] + s[c] ),  s = dinv * (h@W)
// h' = relu(agg + b)

#define HID 64
#define MAXN 100000

__device__ float g_deg [MAXN];
__device__ float g_dinv[MAXN];
__device__ float g_s  [MAXN * HID];
__device__ float g_acc[MAXN * HID];
__device__ float g_h  [MAXN * HID];

// ---------------------------------------------------------------------------
// degree: one thread per edge, atomicAdd into deg[col]
__global__ void deg_kernel(const int* __restrict__ col, int n_edges) {
    int i = blockIdx.x * blockDim.x + threadIdx.x;
    if (i < n_edges) atomicAdd(&g_deg[col[i]], 1.0f);
}

// dinv = rsqrt(deg + 1)   (+1 = self loop; always > 0)
__global__ void dinv_kernel(int n_nodes) {
    int i = blockIdx.x * blockDim.x + threadIdx.x;
    if (i < n_nodes) g_dinv[i] = rsqrtf(g_deg[i] + 1.0f);
}

// ---------------------------------------------------------------------------
// s = dinv * (h @ W); acc = s.  blockDim = (64, 4): 4 nodes per block.
template <int IN>
__global__ void gemm_scale_kernel(const float* __restrict__ hin,
                                  const float* __restrict__ W,
                                  int n_nodes) {
    __shared__ float sW[IN * HID];
    __shared__ float sx[4][IN];

    int tx  = threadIdx.x;           // 0..63 : output feature
    int ty  = threadIdx.y;           // 0..3  : node within block
    int tid = ty * 64 + tx;

    for (int i = tid; i < IN * HID; i += 256) sW[i] = W[i];

    int node0 = blockIdx.x * 4;
    for (int i = tid; i < 4 * IN; i += 256) {
        int nn = node0 + i / IN;
        sx[i / IN][i % IN] = (nn < n_nodes) ? hin[nn * IN + (i % IN)] : 0.0f;
    }
    __syncthreads();

    int node = node0 + ty;
    if (node >= n_nodes) return;

    float acc = 0.0f;
#pragma unroll
    for (int k = 0; k < IN; k++)
        acc = fmaf(sx[ty][k], sW[k * HID + tx], acc);

    float v = g_dinv[node] * acc;
    g_s  [node * HID + tx] = v;
    g_acc[node * HID + tx] = v;   // self-loop term pre-seeded
}

// ---------------------------------------------------------------------------
// scatter: one warp per edge. lane l handles features l and l+32.
__global__ void scatter_kernel(const int* __restrict__ row,
                               const int* __restrict__ col,
                               int n_edges) {
    int gid  = blockIdx.x * blockDim.x + threadIdx.x;
    int e    = gid >> 5;
    int lane = gid & 31;
    if (e >= n_edges) return;
    int r = __ldg(&row[e]);
    int c = __ldg(&col[e]);
    float v0 = __ldg(&g_s[r * HID + lane]);
    float v1 = __ldg(&g_s[r * HID + 32 + lane]);
    atomicAdd(&g_acc[c * HID + lane],      v0);
    atomicAdd(&g_acc[c * HID + 32 + lane], v1);
}

// ---------------------------------------------------------------------------
// h' = relu(dinv * acc + b)
__global__ void finalize_kernel(const float* __restrict__ b,
                                float* __restrict__ hout,
                                int n_nodes) {
    int i = blockIdx.x * blockDim.x + threadIdx.x;
    if (i >= n_nodes * HID) return;
    int node = i >> 6;
    int f    = i & 63;
    float v  = fmaf(g_dinv[node], g_acc[i], b[f]);
    hout[i]  = fmaxf(v, 0.0f);
}

// ---------------------------------------------------------------------------
extern "C" void kernel_launch(void* const* d_in, const int* in_sizes, int n_in,
                              void* d_out, int out_size) {
    const float* x  = (const float*)d_in[0];
    const int*   ei = (const int*)  d_in[1];
    const float* W[5] = { (const float*)d_in[2], (const float*)d_in[4],
                          (const float*)d_in[6], (const float*)d_in[8],
                          (const float*)d_in[10] };
    const float* B[5] = { (const float*)d_in[3], (const float*)d_in[5],
                          (const float*)d_in[7], (const float*)d_in[9],
                          (const float*)d_in[11] };
    float* out = (float*)d_out;

    int n_nodes = in_sizes[0] / 128;
    int n_edges = in_sizes[1] / 2;
    const int* row = ei;
    const int* col = ei + n_edges;

    float* deg_ptr = nullptr;
    cudaGetSymbolAddress((void**)&deg_ptr, g_deg);
    cudaMemsetAsync(deg_ptr, 0, n_nodes * sizeof(float));

    deg_kernel<<<(n_edges + 255) / 256, 256>>>(col, n_edges);
    dinv_kernel<<<(n_nodes + 255) / 256, 256>>>(n_nodes);

    int gemm_blocks   = (n_nodes + 3) / 4;
    dim3 gemm_block(64, 4);
    long scat_threads = (long)n_edges * 32;
    int  scat_blocks  = (int)((scat_threads + 255) / 256);
    int  fin_blocks   = (n_nodes * HID + 255) / 256;

    float* h_ptr = nullptr;
    cudaGetSymbolAddress((void**)&h_ptr, g_h);

    for (int layer = 0; layer < 5; layer++) {
        if (layer == 0)
            gemm_scale_kernel<128><<<gemm_blocks, gemm_block>>>(x, W[0], n_nodes);
        else
            gemm_scale_kernel<64><<<gemm_blocks, gemm_block>>>(h_ptr, W[layer], n_nodes);

        scatter_kernel<<<scat_blocks, 256>>>(row, col, n_edges);

        float* dst = (layer == 4) ? out : h_ptr;
        finalize_kernel<<<fin_blocks, 256>>>(B[layer], dst, n_nodes);
    }
}

// round 3
// speedup vs baseline: 4.0722x; 4.0722x over previous
#include <cuda_runtime.h>
#include <cuda_bf16.h>

// 5-layer GCN, N=100000, E=1.6M, 128->64->64->64->64->64.
// Per layer:  s = dinv * (h@W)           (register-tiled fp32 GEMM)
//             h' = relu(dinv*(sum_{in} s[row] + s) + b)   (CSR gather, fused)
// CSR (grouped by destination col) built once per launch: histogram + scan + fill.

#define HID   64
#define MAXN  100000
#define MAXE  1600000
#define SCAN_B 512
#define MAXSCANB 256

static_assert((MAXN + SCAN_B - 1) / SCAN_B <= MAXSCANB, "scan capacity");

__device__ int   g_deg [MAXN];
__device__ int   g_ptr [MAXN + 1];
__device__ int   g_cur [MAXN];
__device__ int   g_csr [MAXE];
__device__ int   g_bsum[MAXSCANB];
__device__ float g_dinv[MAXN];
__device__ float g_s   [MAXN * HID];
__device__ float g_h   [MAXN * HID];

// ---------------------------------------------------------------- CSR build
__global__ void deg_kernel(const int* __restrict__ col, int n_edges) {
    int i = blockIdx.x * blockDim.x + threadIdx.x;
    if (i < n_edges) atomicAdd(&g_deg[col[i]], 1);
}

__global__ void dinv_kernel(int n_nodes) {
    int i = blockIdx.x * blockDim.x + threadIdx.x;
    if (i < n_nodes) g_dinv[i] = rsqrtf((float)g_deg[i] + 1.0f);  // +1 self loop
}

// block-local inclusive scan of degrees -> g_ptr[i+1]; block totals -> g_bsum
__global__ void __launch_bounds__(SCAN_B) scan1_kernel(int n) {
    __shared__ int sh[SCAN_B];
    int i = blockIdx.x * SCAN_B + threadIdx.x;
    int v = (i < n) ? g_deg[i] : 0;
    sh[threadIdx.x] = v;
    __syncthreads();
#pragma unroll
    for (int off = 1; off < SCAN_B; off <<= 1) {
        int t = (threadIdx.x >= off) ? sh[threadIdx.x - off] : 0;
        __syncthreads();
        sh[threadIdx.x] += t;
        __syncthreads();
    }
    if (i < n) g_ptr[i + 1] = sh[threadIdx.x];
    if (threadIdx.x == SCAN_B - 1) g_bsum[blockIdx.x] = sh[threadIdx.x];
}

// exclusive scan of block sums (single block of 256)
__global__ void __launch_bounds__(MAXSCANB) scan2_kernel(int nb) {
    __shared__ int sh[MAXSCANB];
    int v = (threadIdx.x < nb) ? g_bsum[threadIdx.x] : 0;
    sh[threadIdx.x] = v;
    __syncthreads();
#pragma unroll
    for (int off = 1; off < MAXSCANB; off <<= 1) {
        int t = (threadIdx.x >= off) ? sh[threadIdx.x - off] : 0;
        __syncthreads();
        sh[threadIdx.x] += t;
        __syncthreads();
    }
    if (threadIdx.x < nb) g_bsum[threadIdx.x] = sh[threadIdx.x] - v;  // exclusive
}

// add block offsets; produce cursor = exclusive ptr
__global__ void scan3_kernel(int n) {
    int i = blockIdx.x * blockDim.x + threadIdx.x;
    if (i < n) {
        int val = g_ptr[i + 1] + g_bsum[i / SCAN_B];
        g_ptr[i + 1] = val;
        g_cur[i]     = val - g_deg[i];
    }
    if (i == 0) g_ptr[0] = 0;
}

__global__ void fill_kernel(const int* __restrict__ row,
                            const int* __restrict__ col, int n_edges) {
    int e = blockIdx.x * blockDim.x + threadIdx.x;
    if (e < n_edges) {
        int pos = atomicAdd(&g_cur[col[e]], 1);
        g_csr[pos] = row[e];
    }
}

// ---------------------------------------------------------------- GEMM
// s[node][f] = dinv[node] * sum_k h[node][k] * W[k][f]
// 64x64 output tile per 256-thread block, 4x4 register tile per thread.
template <int IN>
__global__ void __launch_bounds__(256) gemm_scale_kernel(
        const float* __restrict__ hin,
        const float* __restrict__ W,
        int n_nodes) {
    __shared__ float sA[64][64];   // [node][k]
    __shared__ float sW[64][64];   // [k][feat]

    int tid   = threadIdx.x;
    int node0 = blockIdx.x * 64;
    int tx    = tid & 15;          // feature quad
    int ty    = tid >> 4;          // node quad

    float acc[4][4];
#pragma unroll
    for (int m = 0; m < 4; m++)
#pragma unroll
        for (int q = 0; q < 4; q++) acc[m][q] = 0.0f;

    for (int kt = 0; kt < IN; kt += 64) {
        for (int i = tid; i < 64 * 16; i += 256) {
            int nn = i >> 4;
            int kk = (i & 15) << 2;
            int gn = node0 + nn;
            float4 v = make_float4(0.f, 0.f, 0.f, 0.f);
            if (gn < n_nodes)
                v = *(const float4*)&hin[(long)gn * IN + kt + kk];
            *(float4*)&sA[nn][kk] = v;
        }
        for (int i = tid; i < 64 * 16; i += 256) {
            int kk = i >> 4;
            int ff = (i & 15) << 2;
            *(float4*)&sW[kk][ff] = *(const float4*)&W[(kt + kk) * HID + ff];
        }
        __syncthreads();

#pragma unroll
        for (int k = 0; k < 64; k++) {
            float4 w = *(float4*)&sW[k][tx * 4];
            float a0 = sA[ty * 4 + 0][k];
            float a1 = sA[ty * 4 + 1][k];
            float a2 = sA[ty * 4 + 2][k];
            float a3 = sA[ty * 4 + 3][k];
            acc[0][0] = fmaf(a0, w.x, acc[0][0]); acc[0][1] = fmaf(a0, w.y, acc[0][1]);
            acc[0][2] = fmaf(a0, w.z, acc[0][2]); acc[0][3] = fmaf(a0, w.w, acc[0][3]);
            acc[1][0] = fmaf(a1, w.x, acc[1][0]); acc[1][1] = fmaf(a1, w.y, acc[1][1]);
            acc[1][2] = fmaf(a1, w.z, acc[1][2]); acc[1][3] = fmaf(a1, w.w, acc[1][3]);
            acc[2][0] = fmaf(a2, w.x, acc[2][0]); acc[2][1] = fmaf(a2, w.y, acc[2][1]);
            acc[2][2] = fmaf(a2, w.z, acc[2][2]); acc[2][3] = fmaf(a2, w.w, acc[2][3]);
            acc[3][0] = fmaf(a3, w.x, acc[3][0]); acc[3][1] = fmaf(a3, w.y, acc[3][1]);
            acc[3][2] = fmaf(a3, w.z, acc[3][2]); acc[3][3] = fmaf(a3, w.w, acc[3][3]);
        }
        __syncthreads();
    }

#pragma unroll
    for (int m = 0; m < 4; m++) {
        int node = node0 + ty * 4 + m;
        if (node < n_nodes) {
            float dv = g_dinv[node];
            float4 o = make_float4(acc[m][0] * dv, acc[m][1] * dv,
                                   acc[m][2] * dv, acc[m][3] * dv);
            *(float4*)&g_s[(long)node * HID + tx * 4] = o;
        }
    }
}

// ---------------------------------------------------------------- aggregate
// warp per node: h'[c] = relu(dinv[c] * (sum_in s[row] + s[c]) + b)
__global__ void __launch_bounds__(256) agg_kernel(
        const float* __restrict__ b,
        float* __restrict__ hout, int n_nodes) {
    int gw   = (blockIdx.x * blockDim.x + threadIdx.x) >> 5;
    int lane = threadIdx.x & 31;
    if (gw >= n_nodes) return;
    int c = gw;

    int beg = g_ptr[c];
    int end = g_ptr[c + 1];

    float a0 = __ldg(&g_s[(long)c * HID + lane]);        // self loop
    float a1 = __ldg(&g_s[(long)c * HID + 32 + lane]);

    for (int j = beg; j < end; j += 32) {
        int rem = end - j;
        int r   = (lane < rem) ? __ldg(&g_csr[j + lane]) : 0;
        int cnt = min(32, rem);
        int t = 0;
        for (; t + 4 <= cnt; t += 4) {
            int r0 = __shfl_sync(0xffffffffu, r, t + 0);
            int r1 = __shfl_sync(0xffffffffu, r, t + 1);
            int r2 = __shfl_sync(0xffffffffu, r, t + 2);
            int r3 = __shfl_sync(0xffffffffu, r, t + 3);
            float v00 = __ldg(&g_s[(long)r0 * HID + lane]);
            float v01 = __ldg(&g_s[(long)r0 * HID + 32 + lane]);
            float v10 = __ldg(&g_s[(long)r1 * HID + lane]);
            float v11 = __ldg(&g_s[(long)r1 * HID + 32 + lane]);
            float v20 = __ldg(&g_s[(long)r2 * HID + lane]);
            float v21 = __ldg(&g_s[(long)r2 * HID + 32 + lane]);
            float v30 = __ldg(&g_s[(long)r3 * HID + lane]);
            float v31 = __ldg(&g_s[(long)r3 * HID + 32 + lane]);
            a0 += v00; a1 += v01;
            a0 += v10; a1 += v11;
            a0 += v20; a1 += v21;
            a0 += v30; a1 += v31;
        }
        for (; t < cnt; t++) {
            int rr = __shfl_sync(0xffffffffu, r, t);
            a0 += __ldg(&g_s[(long)rr * HID + lane]);
            a1 += __ldg(&g_s[(long)rr * HID + 32 + lane]);
        }
    }

    float dv = g_dinv[c];
    float o0 = fmaf(dv, a0, __ldg(&b[lane]));
    float o1 = fmaf(dv, a1, __ldg(&b[32 + lane]));
    hout[(long)c * HID + lane]      = fmaxf(o0, 0.0f);
    hout[(long)c * HID + 32 + lane] = fmaxf(o1, 0.0f);
}

// ---------------------------------------------------------------- launch
extern "C" void kernel_launch(void* const* d_in, const int* in_sizes, int n_in,
                              void* d_out, int out_size) {
    const float* x  = (const float*)d_in[0];
    const int*   ei = (const int*)  d_in[1];
    const float* W[5] = { (const float*)d_in[2], (const float*)d_in[4],
                          (const float*)d_in[6], (const float*)d_in[8],
                          (const float*)d_in[10] };
    const float* B[5] = { (const float*)d_in[3], (const float*)d_in[5],
                          (const float*)d_in[7], (const float*)d_in[9],
                          (const float*)d_in[11] };
    float* out = (float*)d_out;

    int n_nodes = in_sizes[0] / 128;
    int n_edges = in_sizes[1] / 2;
    const int* row = ei;
    const int* col = ei + n_edges;

    void* deg_ptr = nullptr;
    cudaGetSymbolAddress(&deg_ptr, g_deg);
    cudaMemsetAsync(deg_ptr, 0, n_nodes * sizeof(int));

    float* h_ptr = nullptr;
    cudaGetSymbolAddress((void**)&h_ptr, g_h);

    // CSR build
    deg_kernel <<<(n_edges + 255) / 256, 256>>>(col, n_edges);
    dinv_kernel<<<(n_nodes + 255) / 256, 256>>>(n_nodes);
    int nscan = (n_nodes + SCAN_B - 1) / SCAN_B;
    scan1_kernel<<<nscan, SCAN_B>>>(n_nodes);
    scan2_kernel<<<1, MAXSCANB>>>(nscan);
    scan3_kernel<<<(n_nodes + 255) / 256, 256>>>(n_nodes);
    fill_kernel <<<(n_edges + 255) / 256, 256>>>(row, col, n_edges);

    int gemm_blocks = (n_nodes + 63) / 64;
    int agg_blocks  = (n_nodes * 32 + 255) / 256;

    for (int layer = 0; layer < 5; layer++) {
        if (layer == 0)
            gemm_scale_kernel<128><<<gemm_blocks, 256>>>(x, W[0], n_nodes);
        else
            gemm_scale_kernel<64><<<gemm_blocks, 256>>>(h_ptr, W[layer], n_nodes);

        float* dst = (layer == 4) ? out : h_ptr;
        agg_kernel<<<agg_blocks, 256>>>(B[layer], dst, n_nodes);
    }
}